// round 1
// baseline (speedup 1.0000x reference)
#include <cuda_runtime.h>
#include <cuda_bf16.h>

// PackedAvgPool1d: ragged packed 1D average pooling.
//   x:        [total_tokens, DIM] float32 (packed over batch)
//   seq_lens: [BATCH] int32
//   kernel_size, stride: int32 scalars (device, size 1)
//   out:      [total_y, DIM] float32 where y_len(b) = ceil_div(max(L-K,0),S)+1 (0 if L==0)
//
// DIM = 768 (structural constant of this problem) -> 192 float4 per row.
// One thread produces one output float4: up to K coalesced float4 loads + 1 store.

#define POOL_DIM 768
#define POOL_D4  (POOL_DIM / 4)
#define MAX_BATCH 128

__global__ void __launch_bounds__(256) packed_avgpool_kernel(
    const float4* __restrict__ x,
    const int*    __restrict__ seq_lens,
    const int*    __restrict__ pK,
    const int*    __restrict__ pS,
    float4*       __restrict__ out,
    int batch,
    int n4_total)
{
    __shared__ int s_xcu[MAX_BATCH + 1];   // input-token prefix sums
    __shared__ int s_ycu[MAX_BATCH + 1];   // output-token prefix sums
    __shared__ int s_K, s_S;

    const int tid = threadIdx.x;

    if (tid == 0) {
        s_K = pK ? *pK : 2;
        s_S = pS ? *pS : 2;
    }
    // Deposit raw lengths, then thread 0 builds both prefix tables serially
    // (batch is tiny; this is ~32 adds per block, amortized over 256 threads).
    if (tid < batch) {
        s_xcu[tid + 1] = seq_lens[tid];
    }
    __syncthreads();
    if (tid == 0) {
        const int K = s_K, S = s_S;
        int xa = 0, ya = 0;
        s_xcu[0] = 0;
        s_ycu[0] = 0;
        for (int b = 0; b < batch; ++b) {
            const int L = s_xcu[b + 1];          // raw length (not yet overwritten)
            int yl = 0;
            if (L > 0) {
                int num = L - K; if (num < 0) num = 0;
                yl = (num + S - 1) / S + 1;
            }
            xa += L;
            ya += yl;
            s_xcu[b + 1] = xa;
            s_ycu[b + 1] = ya;
        }
    }
    __syncthreads();

    const int idx = blockIdx.x * blockDim.x + tid;
    if (idx >= n4_total) return;

    const int row = idx / POOL_D4;
    const int c   = idx - row * POOL_D4;

    // Binary search: largest b with y_cu[b] <= row. Neighboring threads share
    // rows, so shared reads are broadcasts.
    int lo = 0, hi = batch;
    while (hi - lo > 1) {
        const int mid = (lo + hi) >> 1;
        if (s_ycu[mid] <= row) lo = mid; else hi = mid;
    }
    const int b    = lo;
    const int j    = row - s_ycu[b];
    const int base = s_xcu[b];
    const int L    = s_xcu[b + 1] - base;
    const int K    = s_K;
    const int S    = s_S;
    const int p0   = j * S;

    float4 r;
    if (K == 2 && S == 2) {
        // Fast path: window start p0 = 2j is always valid (j < ceil(L/2)).
        const float4 v0 = x[(size_t)(base + p0) * POOL_D4 + c];
        if (p0 + 1 < L) {
            const float4 v1 = x[(size_t)(base + p0 + 1) * POOL_D4 + c];
            r.x = (v0.x + v1.x) * 0.5f;
            r.y = (v0.y + v1.y) * 0.5f;
            r.z = (v0.z + v1.z) * 0.5f;
            r.w = (v0.w + v1.w) * 0.5f;
        } else {
            r = v0;
        }
    } else {
        float ax = 0.f, ay = 0.f, az = 0.f, aw = 0.f;
        int cnt = 0;
        for (int k = 0; k < K; ++k) {
            const int p = p0 + k;
            if (p < L) {
                const float4 v = x[(size_t)(base + p) * POOL_D4 + c];
                ax += v.x; ay += v.y; az += v.z; aw += v.w;
                ++cnt;
            }
        }
        const float inv = (cnt > 0) ? (1.0f / (float)cnt) : 0.0f;
        r.x = ax * inv; r.y = ay * inv; r.z = az * inv; r.w = aw * inv;
    }

    out[idx] = r;
}

extern "C" void kernel_launch(void* const* d_in, const int* in_sizes, int n_in,
                              void* d_out, int out_size)
{
    const float4* x        = (const float4*)d_in[0];
    const int*    seq_lens = (const int*)d_in[1];
    const int*    pK       = (n_in >= 3) ? (const int*)d_in[2] : nullptr;
    const int*    pS       = (n_in >= 4) ? (const int*)d_in[3] : nullptr;
    float4*       out      = (float4*)d_out;

    const int batch    = in_sizes[1];
    const int n4_total = out_size / 4;      // out_size is total_y * 768, 768 % 4 == 0

    const int threads = 256;
    const int blocks  = (n4_total + threads - 1) / threads;
    packed_avgpool_kernel<<<blocks, threads>>>(x, seq_lens, pK, pS, out,
                                               batch, n4_total);
}

// round 2
// speedup vs baseline: 2.1919x; 2.1919x over previous
#include <cuda_runtime.h>
#include <cuda_bf16.h>

// PackedAvgPool1d — three-phase streaming design.
//   Phase 1 (1 thread): build input/output prefix tables from seq_lens, read K/S.
//   Phase 2 (grid-stride): per output row, precompute packed meta:
//              meta = src_input_row | (valid_tap_count << 24)
//   Phase 3 (streaming): each thread = one (row, float4-column); reads meta
//              (broadcast), does cnt coalesced float4 loads + 1 store.
// DIM = 768 -> 192 float4 per row.

#define POOL_D4   192
#define MAX_BATCH 1024
#define MAX_ROWS  (1 << 20)   // 4 MB scratch, >> 40448 actual rows

__device__ int g_xcu[MAX_BATCH + 1];
__device__ int g_ycu[MAX_BATCH + 1];
__device__ int g_KS[2];
__device__ int g_meta[MAX_ROWS];

// ---- Phase 1: serial prefix build (runs once per replay, trivial cost) ----
__global__ void pool_setup_kernel(const int* __restrict__ seq_lens,
                                  const int* __restrict__ pK,
                                  const int* __restrict__ pS,
                                  int batch)
{
    if (threadIdx.x != 0 || blockIdx.x != 0) return;
    const int K = pK ? *pK : 2;
    const int S = pS ? *pS : 2;
    g_KS[0] = K;
    g_KS[1] = S;
    int xa = 0, ya = 0;
    g_xcu[0] = 0;
    g_ycu[0] = 0;
    for (int b = 0; b < batch; ++b) {
        const int L = seq_lens[b];
        int yl = 0;
        if (L > 0) {
            int num = L - K; if (num < 0) num = 0;
            yl = (num + S - 1) / S + 1;
        }
        xa += L;
        ya += yl;
        g_xcu[b + 1] = xa;
        g_ycu[b + 1] = ya;
    }
}

// ---- Phase 2: per-row meta (src row + valid tap count) ----
__global__ void __launch_bounds__(256) pool_meta_kernel(int batch, int n_rows)
{
    __shared__ int s_ycu[MAX_BATCH + 1];
    __shared__ int s_xcu[MAX_BATCH + 1];
    for (int i = threadIdx.x; i <= batch; i += blockDim.x) {
        s_ycu[i] = g_ycu[i];
        s_xcu[i] = g_xcu[i];
    }
    __syncthreads();
    const int K = g_KS[0];
    const int S = g_KS[1];
    for (int row = blockIdx.x * blockDim.x + threadIdx.x; row < n_rows;
         row += gridDim.x * blockDim.x) {
        int lo = 0, hi = batch;
        while (hi - lo > 1) {
            const int mid = (lo + hi) >> 1;
            if (s_ycu[mid] <= row) lo = mid; else hi = mid;
        }
        const int b    = lo;
        const int j    = row - s_ycu[b];
        const int base = s_xcu[b];
        const int L    = s_xcu[b + 1] - base;
        const int p0   = j * S;
        int cnt = L - p0; if (cnt > K) cnt = K; if (cnt < 1) cnt = 1;
        g_meta[row] = (base + p0) | (cnt << 24);
    }
}

// ---- Phase 3: streaming pool. blockDim = (192, 4): 4 rows per block. ----
__global__ void __launch_bounds__(768) pool_main_kernel(
    const float4* __restrict__ x,
    float4*       __restrict__ out,
    int n_rows)
{
    const int row = blockIdx.x * 4 + threadIdx.y;
    if (row >= n_rows) return;
    const int c = threadIdx.x;

    const int meta = g_meta[row];          // broadcast across the 192 lanes
    const int src  = meta & 0xFFFFFF;
    const int cnt  = meta >> 24;

    const size_t sbase = (size_t)src * POOL_D4 + c;
    float4 a = x[sbase];
    if (cnt == 2) {                         // dominant case for K=2,S=2
        const float4 v = x[sbase + POOL_D4];
        a.x = (a.x + v.x) * 0.5f;
        a.y = (a.y + v.y) * 0.5f;
        a.z = (a.z + v.z) * 0.5f;
        a.w = (a.w + v.w) * 0.5f;
    } else if (cnt > 2) {                   // general K fallback
        for (int k = 1; k < cnt; ++k) {
            const float4 v = x[sbase + (size_t)k * POOL_D4];
            a.x += v.x; a.y += v.y; a.z += v.z; a.w += v.w;
        }
        const float inv = 1.0f / (float)cnt;
        a.x *= inv; a.y *= inv; a.z *= inv; a.w *= inv;
    }
    out[(size_t)row * POOL_D4 + c] = a;
}

extern "C" void kernel_launch(void* const* d_in, const int* in_sizes, int n_in,
                              void* d_out, int out_size)
{
    const float4* x        = (const float4*)d_in[0];
    const int*    seq_lens = (const int*)d_in[1];
    const int*    pK       = (n_in >= 3) ? (const int*)d_in[2] : nullptr;
    const int*    pS       = (n_in >= 4) ? (const int*)d_in[3] : nullptr;
    float4*       out      = (float4*)d_out;

    const int batch  = in_sizes[1];
    const int n_rows = out_size / 768;

    pool_setup_kernel<<<1, 1>>>(seq_lens, pK, pS, batch);
    pool_meta_kernel<<<160, 256>>>(batch, n_rows);

    dim3 blk(192, 4);
    const int grid = (n_rows + 3) / 4;
    pool_main_kernel<<<grid, blk>>>(x, out, n_rows);
}

// round 3
// speedup vs baseline: 2.7178x; 1.2399x over previous
#include <cuda_runtime.h>
#include <cuda_bf16.h>

// PackedAvgPool1d — two-phase streaming design.
//   Phase A (meta): per-block warp-scan of seq_lens -> prefix tables in smem,
//                   then per output row pack meta = src_row | (tap_count<<24).
//   Phase B (main): pure streaming; thread = (row, float4-col). 1 broadcast
//                   meta load + cnt coalesced float4 loads + 1 store.
// DIM = 768 -> 192 float4 per row.

#define POOL_D4   192
#define MAX_BATCH 1024
#define MAX_ROWS  (1 << 20)
#define FULLMASK  0xFFFFFFFFu

__device__ int g_meta[MAX_ROWS];

// ---- Phase A: prefix scan + per-row meta, one kernel ----
__global__ void __launch_bounds__(256) pool_meta_kernel(
    const int* __restrict__ seq_lens,
    const int* __restrict__ pK,
    const int* __restrict__ pS,
    int batch, int n_rows)
{
    __shared__ int s_xcu[MAX_BATCH + 1];
    __shared__ int s_ycu[MAX_BATCH + 1];

    const int K = pK ? __ldg(pK) : 2;
    const int S = pS ? __ldg(pS) : 2;

    // Warp 0 builds both prefix tables via inclusive warp scans (chunks of 32).
    if (threadIdx.x < 32) {
        const int lane = threadIdx.x;
        int xoff = 0, yoff = 0;
        if (lane == 0) { s_xcu[0] = 0; s_ycu[0] = 0; }
        for (int chunk = 0; chunk < batch; chunk += 32) {
            const int i = chunk + lane;
            int L = (i < batch) ? seq_lens[i] : 0;
            int yl = 0;
            if (L > 0) {
                int num = L - K; if (num < 0) num = 0;
                yl = (num + S - 1) / S + 1;
            }
            int xs = L, ys = yl;
            #pragma unroll
            for (int d = 1; d < 32; d <<= 1) {
                const int nx = __shfl_up_sync(FULLMASK, xs, d);
                const int ny = __shfl_up_sync(FULLMASK, ys, d);
                if (lane >= d) { xs += nx; ys += ny; }
            }
            if (i < batch) {
                s_xcu[i + 1] = xoff + xs;
                s_ycu[i + 1] = yoff + ys;
            }
            xoff += __shfl_sync(FULLMASK, xs, 31);
            yoff += __shfl_sync(FULLMASK, ys, 31);
        }
    }
    __syncthreads();

    for (int row = blockIdx.x * blockDim.x + threadIdx.x; row < n_rows;
         row += gridDim.x * blockDim.x) {
        int lo = 0, hi = batch;
        while (hi - lo > 1) {
            const int mid = (lo + hi) >> 1;
            if (s_ycu[mid] <= row) lo = mid; else hi = mid;
        }
        const int b    = lo;
        const int j    = row - s_ycu[b];
        const int base = s_xcu[b];
        const int L    = s_xcu[b + 1] - base;
        const int p0   = j * S;
        int cnt = L - p0; if (cnt > K) cnt = K; if (cnt < 1) cnt = 1;
        g_meta[row] = (base + p0) | (cnt << 24);
    }
}

// ---- Phase B: streaming pool. blockDim = (192, 5): 5 rows per block. ----
__global__ void __launch_bounds__(960) pool_main_kernel(
    const float4* __restrict__ x,
    float4*       __restrict__ out,
    int n_rows)
{
    const int row = blockIdx.x * 5 + threadIdx.y;
    if (row >= n_rows) return;
    const int c = threadIdx.x;

    const int meta = g_meta[row];          // one sector, broadcast to 192 lanes
    const int src  = meta & 0xFFFFFF;
    const int cnt  = meta >> 24;

    const size_t sbase = (size_t)src * POOL_D4 + c;
    float4 a = __ldcs(&x[sbase]);          // evict-first: x is read exactly once
    if (cnt == 2) {                         // dominant case for K=2,S=2
        const float4 v = __ldcs(&x[sbase + POOL_D4]);
        a.x = (a.x + v.x) * 0.5f;
        a.y = (a.y + v.y) * 0.5f;
        a.z = (a.z + v.z) * 0.5f;
        a.w = (a.w + v.w) * 0.5f;
    } else if (cnt > 2) {                   // general K fallback
        for (int k = 1; k < cnt; ++k) {
            const float4 v = __ldcs(&x[sbase + (size_t)k * POOL_D4]);
            a.x += v.x; a.y += v.y; a.z += v.z; a.w += v.w;
        }
        const float inv = 1.0f / (float)cnt;
        a.x *= inv; a.y *= inv; a.z *= inv; a.w *= inv;
    }
    __stcs(&out[(size_t)row * POOL_D4 + c], a);   // never re-read: stream it
}

extern "C" void kernel_launch(void* const* d_in, const int* in_sizes, int n_in,
                              void* d_out, int out_size)
{
    const float4* x        = (const float4*)d_in[0];
    const int*    seq_lens = (const int*)d_in[1];
    const int*    pK       = (n_in >= 3) ? (const int*)d_in[2] : nullptr;
    const int*    pS       = (n_in >= 4) ? (const int*)d_in[3] : nullptr;
    float4*       out      = (float4*)d_out;

    const int batch  = in_sizes[1];
    const int n_rows = out_size / 768;
    if (n_rows <= 0) return;

    int meta_blocks = (n_rows + 255) / 256;
    if (meta_blocks > 592) meta_blocks = 592;   // 4 waves of 148 SMs max
    pool_meta_kernel<<<meta_blocks, 256>>>(seq_lens, pK, pS, batch, n_rows);

    dim3 blk(192, 5);
    const int grid = (n_rows + 4) / 5;
    pool_main_kernel<<<grid, blk>>>(x, out, n_rows);
}

// round 4
// speedup vs baseline: 2.8885x; 1.0628x over previous
#include <cuda_runtime.h>
#include <cuda_bf16.h>

// PackedAvgPool1d — two-phase streaming design, MLP-widened main kernel.
//   Phase A (meta): warp-scan prefix tables, pack meta = src_row | (cnt<<24).
//   Phase B (main): blockDim=(96,8); thread = (row, 2 column-chunks).
//                   4 front-batched LDG.128 + 2 STG.128 per thread.
// DIM = 768 -> 192 float4 per row; chunks at c and c+96.

#define POOL_D4   192
#define MAX_BATCH 1024
#define MAX_ROWS  (1 << 20)
#define FULLMASK  0xFFFFFFFFu

__device__ int g_meta[MAX_ROWS];

// ---- Phase A: prefix scan + per-row meta ----
__global__ void __launch_bounds__(256) pool_meta_kernel(
    const int* __restrict__ seq_lens,
    const int* __restrict__ pK,
    const int* __restrict__ pS,
    int batch, int n_rows)
{
    __shared__ int s_xcu[MAX_BATCH + 1];
    __shared__ int s_ycu[MAX_BATCH + 1];

    const int K = pK ? __ldg(pK) : 2;
    const int S = pS ? __ldg(pS) : 2;

    if (threadIdx.x < 32) {
        const int lane = threadIdx.x;
        int xoff = 0, yoff = 0;
        if (lane == 0) { s_xcu[0] = 0; s_ycu[0] = 0; }
        for (int chunk = 0; chunk < batch; chunk += 32) {
            const int i = chunk + lane;
            int L = (i < batch) ? seq_lens[i] : 0;
            int yl = 0;
            if (L > 0) {
                int num = L - K; if (num < 0) num = 0;
                yl = (num + S - 1) / S + 1;
            }
            int xs = L, ys = yl;
            #pragma unroll
            for (int d = 1; d < 32; d <<= 1) {
                const int nx = __shfl_up_sync(FULLMASK, xs, d);
                const int ny = __shfl_up_sync(FULLMASK, ys, d);
                if (lane >= d) { xs += nx; ys += ny; }
            }
            if (i < batch) {
                s_xcu[i + 1] = xoff + xs;
                s_ycu[i + 1] = yoff + ys;
            }
            xoff += __shfl_sync(FULLMASK, xs, 31);
            yoff += __shfl_sync(FULLMASK, ys, 31);
        }
    }
    __syncthreads();

    for (int row = blockIdx.x * blockDim.x + threadIdx.x; row < n_rows;
         row += gridDim.x * blockDim.x) {
        int lo = 0, hi = batch;
        while (hi - lo > 1) {
            const int mid = (lo + hi) >> 1;
            if (s_ycu[mid] <= row) lo = mid; else hi = mid;
        }
        const int b    = lo;
        const int j    = row - s_ycu[b];
        const int base = s_xcu[b];
        const int L    = s_xcu[b + 1] - base;
        const int p0   = j * S;
        int cnt = L - p0; if (cnt > K) cnt = K; if (cnt < 1) cnt = 1;
        g_meta[row] = (base + p0) | (cnt << 24);
    }
}

// ---- Phase B: streaming pool. blockDim=(96,8): 8 rows/block, 2 chunks/thread ----
__global__ void __launch_bounds__(768, 2) pool_main_kernel(
    const float4* __restrict__ x,
    float4*       __restrict__ out,
    int n_rows)
{
    const int row = blockIdx.x * 8 + threadIdx.y;
    if (row >= n_rows) return;
    const int c = threadIdx.x;              // 0..95, chunks at c and c+96

    const int meta = g_meta[row];           // broadcast within the 96-lane group
    const int src  = meta & 0xFFFFFF;
    const int cnt  = meta >> 24;

    const size_t sbase = (size_t)src * POOL_D4 + c;
    // Front-batched independent loads (branch depends only on meta):
    float4 a0 = __ldcs(&x[sbase]);
    float4 a1 = __ldcs(&x[sbase + 96]);

    if (cnt >= 2) {
        float4 b0 = __ldcs(&x[sbase + POOL_D4]);
        float4 b1 = __ldcs(&x[sbase + POOL_D4 + 96]);
        if (cnt == 2) {
            a0.x = (a0.x + b0.x) * 0.5f; a0.y = (a0.y + b0.y) * 0.5f;
            a0.z = (a0.z + b0.z) * 0.5f; a0.w = (a0.w + b0.w) * 0.5f;
            a1.x = (a1.x + b1.x) * 0.5f; a1.y = (a1.y + b1.y) * 0.5f;
            a1.z = (a1.z + b1.z) * 0.5f; a1.w = (a1.w + b1.w) * 0.5f;
        } else {                            // general K fallback (cnt > 2)
            a0.x += b0.x; a0.y += b0.y; a0.z += b0.z; a0.w += b0.w;
            a1.x += b1.x; a1.y += b1.y; a1.z += b1.z; a1.w += b1.w;
            for (int k = 2; k < cnt; ++k) {
                const float4 v0 = __ldcs(&x[sbase + (size_t)k * POOL_D4]);
                const float4 v1 = __ldcs(&x[sbase + (size_t)k * POOL_D4 + 96]);
                a0.x += v0.x; a0.y += v0.y; a0.z += v0.z; a0.w += v0.w;
                a1.x += v1.x; a1.y += v1.y; a1.z += v1.z; a1.w += v1.w;
            }
            const float inv = 1.0f / (float)cnt;
            a0.x *= inv; a0.y *= inv; a0.z *= inv; a0.w *= inv;
            a1.x *= inv; a1.y *= inv; a1.z *= inv; a1.w *= inv;
        }
    }

    const size_t obase = (size_t)row * POOL_D4 + c;
    __stcs(&out[obase], a0);
    __stcs(&out[obase + 96], a1);
}

extern "C" void kernel_launch(void* const* d_in, const int* in_sizes, int n_in,
                              void* d_out, int out_size)
{
    const float4* x        = (const float4*)d_in[0];
    const int*    seq_lens = (const int*)d_in[1];
    const int*    pK       = (n_in >= 3) ? (const int*)d_in[2] : nullptr;
    const int*    pS       = (n_in >= 4) ? (const int*)d_in[3] : nullptr;
    float4*       out      = (float4*)d_out;

    const int batch  = in_sizes[1];
    const int n_rows = out_size / 768;
    if (n_rows <= 0) return;

    int meta_blocks = (n_rows + 255) / 256;
    if (meta_blocks > 592) meta_blocks = 592;
    pool_meta_kernel<<<meta_blocks, 256>>>(seq_lens, pK, pS, batch, n_rows);

    dim3 blk(96, 8);
    const int grid = (n_rows + 7) / 8;
    pool_main_kernel<<<grid, blk>>>(x, out, n_rows);
}

// round 5
// speedup vs baseline: 2.9524x; 1.0221x over previous
#include <cuda_runtime.h>
#include <cuda_bf16.h>

// PackedAvgPool1d — single fused streaming kernel.
//   Per-block prologue (warp 0): parallel shfl-scan of seq_lens -> prefix
//   tables in smem (~700 cyc, overlapped with other resident blocks).
//   Body: thread = (row, 2 column-chunks); binary search smem y_cu (broadcast),
//   then 4 front-batched LDG.128 + 2 STG.128.
// DIM = 768 -> 192 float4 per row; chunks at c and c+96.

#define POOL_D4   192
#define MAX_BATCH 1024
#define FULLMASK  0xFFFFFFFFu

__global__ void __launch_bounds__(384) pool_fused_kernel(
    const float4* __restrict__ x,
    const int*    __restrict__ seq_lens,
    const int*    __restrict__ pK,
    const int*    __restrict__ pS,
    float4*       __restrict__ out,
    int batch, int n_rows)
{
    __shared__ int s_xcu[MAX_BATCH + 1];
    __shared__ int s_ycu[MAX_BATCH + 1];
    __shared__ int s_KS[2];

    const int ltid = threadIdx.y * 96 + threadIdx.x;

    // ---- prologue: warp 0 builds prefix tables via shfl inclusive scan ----
    if (ltid < 32) {
        const int lane = ltid;
        const int K = pK ? __ldg(pK) : 2;
        const int S = pS ? __ldg(pS) : 2;
        if (lane == 0) { s_KS[0] = K; s_KS[1] = S; s_xcu[0] = 0; s_ycu[0] = 0; }
        int xoff = 0, yoff = 0;
        for (int chunk = 0; chunk < batch; chunk += 32) {
            const int i = chunk + lane;
            int L = (i < batch) ? __ldg(&seq_lens[i]) : 0;
            int yl = 0;
            if (L > 0) {
                int num = L - K; if (num < 0) num = 0;
                yl = (num + S - 1) / S + 1;
            }
            int xs = L, ys = yl;
            #pragma unroll
            for (int d = 1; d < 32; d <<= 1) {
                const int nx = __shfl_up_sync(FULLMASK, xs, d);
                const int ny = __shfl_up_sync(FULLMASK, ys, d);
                if (lane >= d) { xs += nx; ys += ny; }
            }
            if (i < batch) {
                s_xcu[i + 1] = xoff + xs;
                s_ycu[i + 1] = yoff + ys;
            }
            xoff += __shfl_sync(FULLMASK, xs, 31);
            yoff += __shfl_sync(FULLMASK, ys, 31);
        }
    }
    __syncthreads();

    const int row = blockIdx.x * 4 + threadIdx.y;
    if (row >= n_rows) return;
    const int c = threadIdx.x;              // 0..95, chunks at c and c+96

    // Binary search: largest b with y_cu[b] <= row (LDS broadcasts).
    int lo = 0, hi = batch;
    while (hi - lo > 1) {
        const int mid = (lo + hi) >> 1;
        if (s_ycu[mid] <= row) lo = mid; else hi = mid;
    }
    const int b    = lo;
    const int j    = row - s_ycu[b];
    const int base = s_xcu[b];
    const int L    = s_xcu[b + 1] - base;
    const int K    = s_KS[0];
    const int S    = s_KS[1];
    const int p0   = j * S;
    int cnt = L - p0; if (cnt > K) cnt = K; if (cnt < 1) cnt = 1;

    const size_t sbase = (size_t)(base + p0) * POOL_D4 + c;
    // Front-batched independent loads (predicate depends only on indices):
    float4 a0 = __ldcs(&x[sbase]);
    float4 a1 = __ldcs(&x[sbase + 96]);

    if (cnt >= 2) {
        float4 b0 = __ldcs(&x[sbase + POOL_D4]);
        float4 b1 = __ldcs(&x[sbase + POOL_D4 + 96]);
        if (cnt == 2) {
            a0.x = (a0.x + b0.x) * 0.5f; a0.y = (a0.y + b0.y) * 0.5f;
            a0.z = (a0.z + b0.z) * 0.5f; a0.w = (a0.w + b0.w) * 0.5f;
            a1.x = (a1.x + b1.x) * 0.5f; a1.y = (a1.y + b1.y) * 0.5f;
            a1.z = (a1.z + b1.z) * 0.5f; a1.w = (a1.w + b1.w) * 0.5f;
        } else {                            // general K fallback (cnt > 2)
            a0.x += b0.x; a0.y += b0.y; a0.z += b0.z; a0.w += b0.w;
            a1.x += b1.x; a1.y += b1.y; a1.z += b1.z; a1.w += b1.w;
            for (int k = 2; k < cnt; ++k) {
                const float4 v0 = __ldcs(&x[sbase + (size_t)k * POOL_D4]);
                const float4 v1 = __ldcs(&x[sbase + (size_t)k * POOL_D4 + 96]);
                a0.x += v0.x; a0.y += v0.y; a0.z += v0.z; a0.w += v0.w;
                a1.x += v1.x; a1.y += v1.y; a1.z += v1.z; a1.w += v1.w;
            }
            const float inv = 1.0f / (float)cnt;
            a0.x *= inv; a0.y *= inv; a0.z *= inv; a0.w *= inv;
            a1.x *= inv; a1.y *= inv; a1.z *= inv; a1.w *= inv;
        }
    }

    const size_t obase = (size_t)row * POOL_D4 + c;
    __stcs(&out[obase], a0);
    __stcs(&out[obase + 96], a1);
}

extern "C" void kernel_launch(void* const* d_in, const int* in_sizes, int n_in,
                              void* d_out, int out_size)
{
    const float4* x        = (const float4*)d_in[0];
    const int*    seq_lens = (const int*)d_in[1];
    const int*    pK       = (n_in >= 3) ? (const int*)d_in[2] : nullptr;
    const int*    pS       = (n_in >= 4) ? (const int*)d_in[3] : nullptr;
    float4*       out      = (float4*)d_out;

    const int batch  = in_sizes[1];
    const int n_rows = out_size / 768;
    if (n_rows <= 0) return;

    dim3 blk(96, 4);
    const int grid = (n_rows + 3) / 4;
    pool_fused_kernel<<<grid, blk>>>(x, seq_lens, pK, pS, out, batch, n_rows);
}